// round 1
// baseline (speedup 1.0000x reference)
#include <cuda_runtime.h>

// Problem constants
#define NB       4
#define TOK      131072          // T*n tokens per batch
#define C        64
#define NROWS    16384           // n
#define SPLITS   256             // split-K blocks per batch
#define TPS      (TOK / SPLITS)  // 512 tokens per split
#define STAGE_T  16              // tokens staged in smem per iteration
#define NSTAGES  (TPS / STAGE_T) // 32

// Scratch (no allocations allowed in kernel_launch)
__device__ float g_partial[(size_t)NB * SPLITS * C * C]; // 16 MB partial kv sums
__device__ float g_kv[NB * C * C];
__device__ float g_sm[NB * C * C];

typedef unsigned long long u64;

// Packed fp32x2 FMA — sm_103a FFMA2, 2x fp32 FMA throughput vs scalar FFMA.
__device__ __forceinline__ u64 fma2(u64 a, u64 b, u64 c) {
    u64 d;
    asm("fma.rn.f32x2 %0, %1, %2, %3;" : "=l"(d) : "l"(a), "l"(b), "l"(c));
    return d;
}
__device__ __forceinline__ u64 pack2(float x, float y) {
    u64 r;
    asm("mov.b64 %0, {%1, %2};" : "=l"(r) : "f"(x), "f"(y));
    return r;
}
__device__ __forceinline__ float2 unpack2(u64 v) {
    float2 r;
    asm("mov.b64 {%0, %1}, %2;" : "=f"(r.x), "=f"(r.y) : "l"(v));
    return r;
}

// ---------------------------------------------------------------------------
// Kernel A: partial kv_mul.  Each block accumulates a full 64x64 outer-product
// sum over TPS tokens.  Keys are staged in smem DUPLICATED ({k,k} pairs) so the
// inner loop is pure LDS.128 + FFMA2 with no per-token packing.
// Thread (cg,dg) owns a 4(c) x 4(d) tile held as 8 f32x2 accumulators.
// ---------------------------------------------------------------------------
__global__ __launch_bounds__(256, 4) void kv_partial_kernel(
    const float* __restrict__ key_mem, const float* __restrict__ val_mem)
{
    // padded rows to spread banks (132*4 % 128 == 16, 68*4 % 128 == 16)
    __shared__ __align__(16) float s_kdup[STAGE_T][132];
    __shared__ __align__(16) float s_v[STAGE_T][68];

    const int b   = blockIdx.y;
    const int s   = blockIdx.x;
    const int tid = threadIdx.x;

    const size_t base = ((size_t)b * TOK + (size_t)s * TPS) * C;
    const float* K = key_mem + base;
    const float* V = val_mem + base;

    const int lrow = tid >> 4;         // staging row   0..15
    const int lcol = (tid & 15) * 4;   // staging col   0..60
    const int c0 = (tid >> 4) * 4;     // tile c origin
    const int d0 = (tid & 15) * 4;     // tile d origin

    u64 acc[4][2];
    #pragma unroll
    for (int i = 0; i < 4; ++i) { acc[i][0] = 0ull; acc[i][1] = 0ull; }

    // prefetch stage 0
    float4 kr = *(const float4*)&K[(size_t)lrow * C + lcol];
    float4 vr = *(const float4*)&V[(size_t)lrow * C + lcol];

    for (int st = 0; st < NSTAGES; ++st) {
        __syncthreads();
        float4* kd = (float4*)&s_kdup[lrow][lcol * 2];
        kd[0] = make_float4(kr.x, kr.x, kr.y, kr.y);
        kd[1] = make_float4(kr.z, kr.z, kr.w, kr.w);
        *(float4*)&s_v[lrow][lcol] = vr;
        __syncthreads();

        if (st + 1 < NSTAGES) { // prefetch next stage (overlaps compute below)
            size_t off = ((size_t)(st + 1) * STAGE_T + lrow) * C + lcol;
            kr = *(const float4*)&K[off];
            vr = *(const float4*)&V[off];
        }

        #pragma unroll
        for (int t = 0; t < STAGE_T; ++t) {
            ulonglong2 kA = *(const ulonglong2*)&s_kdup[t][c0 * 2];     // {k0,k0},{k1,k1}
            ulonglong2 kB = *(const ulonglong2*)&s_kdup[t][c0 * 2 + 4]; // {k2,k2},{k3,k3}
            ulonglong2 vv = *(const ulonglong2*)&s_v[t][d0];            // {v0,v1},{v2,v3}
            acc[0][0] = fma2(kA.x, vv.x, acc[0][0]);
            acc[0][1] = fma2(kA.x, vv.y, acc[0][1]);
            acc[1][0] = fma2(kA.y, vv.x, acc[1][0]);
            acc[1][1] = fma2(kA.y, vv.y, acc[1][1]);
            acc[2][0] = fma2(kB.x, vv.x, acc[2][0]);
            acc[2][1] = fma2(kB.x, vv.y, acc[2][1]);
            acc[3][0] = fma2(kB.y, vv.x, acc[3][0]);
            acc[3][1] = fma2(kB.y, vv.y, acc[3][1]);
        }
    }

    float* out = &g_partial[((size_t)b * SPLITS + s) * (C * C)];
    #pragma unroll
    for (int i = 0; i < 4; ++i) {
        float2 a0 = unpack2(acc[i][0]);
        float2 a1 = unpack2(acc[i][1]);
        *(float4*)&out[(c0 + i) * C + d0] = make_float4(a0.x, a0.y, a1.x, a1.y);
    }
}

// ---------------------------------------------------------------------------
// Kernel B: deterministic reduction of split partials (fixed order).
// ---------------------------------------------------------------------------
__global__ void kv_reduce_kernel()
{
    int e = blockIdx.x * blockDim.x + threadIdx.x;  // 0..16383
    int b  = e >> 12;
    int cd = e & 4095;
    const float* p = &g_partial[(size_t)b * SPLITS * (C * C) + cd];
    float sum = 0.f;
    #pragma unroll 8
    for (int i = 0; i < SPLITS; ++i) sum += p[(size_t)i * (C * C)];
    g_kv[e] = sum;
}

// ---------------------------------------------------------------------------
// Kernel C: softmax over the C axis.  One thread per (b, d) column: exactly
// 4*64 = 256 threads in a single block.
// ---------------------------------------------------------------------------
__global__ void softmax_kernel()
{
    int tid = threadIdx.x;
    int b = tid >> 6;
    int d = tid & 63;
    const float* in = &g_kv[b * (C * C) + d];
    float*       out = &g_sm[b * (C * C) + d];

    float m = -3.402823466e38f;
    for (int c = 0; c < C; ++c) m = fmaxf(m, in[c * C]);
    float sum = 0.f;
    for (int c = 0; c < C; ++c) {
        float e = expf(in[c * C] - m);
        out[c * C] = e;
        sum += e;
    }
    float inv = 1.f / sum;
    for (int c = 0; c < C; ++c) out[c * C] *= inv;
}

// ---------------------------------------------------------------------------
// Kernel D: out[b,r,d] = alpha * sum_c key_cur[b,r,c] * sm[b,c,d] + val_cur.
// Block handles 64 rows; sm (16KB) and key rows (padded) cached in smem.
// Thread (r, dq) computes 16 d-outputs of one row via FFMA2.
// ---------------------------------------------------------------------------
__global__ __launch_bounds__(256) void out_kernel(
    const float* __restrict__ key_cur, const float* __restrict__ val_cur,
    const float* __restrict__ alpha, float* __restrict__ out)
{
    __shared__ __align__(16) float s_sm[C * C];   // [c][d]
    __shared__ float s_key[C * 65];               // padded rows

    const int b   = blockIdx.y;
    const int rb  = blockIdx.x;        // 0..255
    const int tid = threadIdx.x;
    const int r0  = rb * 64;

    // load softmaxed kv matrix
    const float* smg = &g_sm[b * (C * C)];
    #pragma unroll
    for (int j = 0; j < 4; ++j) {
        int idx = tid * 16 + j * 4;
        *(float4*)&s_sm[idx] = *(const float4*)&smg[idx];
    }
    // load 64 key_cur rows into padded smem
    const float* kg = &key_cur[((size_t)b * NROWS + r0) * C];
    #pragma unroll
    for (int j = 0; j < 4; ++j) {
        int e = tid * 16 + j * 4;
        float4 v = *(const float4*)&kg[e];
        int i = e >> 6, c = e & 63;
        float* dst = &s_key[i * 65 + c];
        dst[0] = v.x; dst[1] = v.y; dst[2] = v.z; dst[3] = v.w;
    }
    __syncthreads();

    const int r  = tid >> 2;
    const int dq = (tid & 3) * 16;

    u64 acc[8];
    #pragma unroll
    for (int i = 0; i < 8; ++i) acc[i] = 0ull;

    const float* krow = &s_key[r * 65];
    #pragma unroll 4
    for (int c = 0; c < C; ++c) {
        float k = krow[c];
        u64 kk = pack2(k, k);
        const ulonglong2* sp = (const ulonglong2*)&s_sm[c * C + dq];
        ulonglong2 s0 = sp[0], s1 = sp[1], s2 = sp[2], s3 = sp[3];
        acc[0] = fma2(kk, s0.x, acc[0]);
        acc[1] = fma2(kk, s0.y, acc[1]);
        acc[2] = fma2(kk, s1.x, acc[2]);
        acc[3] = fma2(kk, s1.y, acc[3]);
        acc[4] = fma2(kk, s2.x, acc[4]);
        acc[5] = fma2(kk, s2.y, acc[5]);
        acc[6] = fma2(kk, s3.x, acc[6]);
        acc[7] = fma2(kk, s3.y, acc[7]);
    }

    const float a = alpha[0];
    const size_t obase = ((size_t)b * NROWS + r0 + r) * C + dq;
    #pragma unroll
    for (int j = 0; j < 4; ++j) {
        float4 vc = *(const float4*)&val_cur[obase + j * 4];
        float2 x0 = unpack2(acc[j * 2]);
        float2 x1 = unpack2(acc[j * 2 + 1]);
        float4 o;
        o.x = a * x0.x + vc.x;
        o.y = a * x0.y + vc.y;
        o.z = a * x1.x + vc.z;
        o.w = a * x1.y + vc.w;
        *(float4*)&out[obase + j * 4] = o;
    }
}

// ---------------------------------------------------------------------------
extern "C" void kernel_launch(void* const* d_in, const int* in_sizes, int n_in,
                              void* d_out, int out_size)
{
    const float* key_mem = (const float*)d_in[0];
    const float* val_mem = (const float*)d_in[1];
    const float* key_cur = (const float*)d_in[2];
    const float* val_cur = (const float*)d_in[3];
    const float* alpha   = (const float*)d_in[4];
    float* out = (float*)d_out;

    kv_partial_kernel<<<dim3(SPLITS, NB), 256>>>(key_mem, val_mem);
    kv_reduce_kernel<<<64, 256>>>();
    softmax_kernel<<<1, 256>>>();
    out_kernel<<<dim3(NROWS / 64, NB), 256>>>(key_cur, val_cur, alpha, out);
}

// round 2
// speedup vs baseline: 1.4342x; 1.4342x over previous
#include <cuda_runtime.h>

// Problem constants
#define NB       4
#define TOK      131072          // T*n tokens per batch
#define C        64
#define NROWS    16384           // n
#define SPLITS   128             // split-K blocks per batch
#define TPS      (TOK / SPLITS)  // 1024 tokens per block
#define NGROUPS  4               // split-K sub-groups within a block
#define TPG      (TPS / NGROUPS) // 256 tokens per sub-group
#define STAGE_T  8               // tokens per sub-group per pipeline stage
#define NSTAGES  (TPG / STAGE_T) // 32
#define RP       68              // padded row length (floats), 16B-aligned stride

// Scratch (no allocations allowed)
__device__ float g_partial[(size_t)NB * SPLITS * C * C]; // 8 MB partial kv sums
__device__ float g_kv[NB * C * C];
__device__ float g_sm[NB * C * C];

typedef unsigned long long u64;

// Packed fp32x2 ops (sm_103a FFMA2 path — 2x fp32 FMA throughput)
__device__ __forceinline__ u64 fma2(u64 a, u64 b, u64 c) {
    u64 d;
    asm("fma.rn.f32x2 %0, %1, %2, %3;" : "=l"(d) : "l"(a), "l"(b), "l"(c));
    return d;
}
__device__ __forceinline__ u64 add2(u64 a, u64 b) {
    u64 d;
    asm("add.rn.f32x2 %0, %1, %2;" : "=l"(d) : "l"(a), "l"(b));
    return d;
}
__device__ __forceinline__ u64 pack2(float x, float y) {
    u64 r;
    asm("mov.b64 %0, {%1, %2};" : "=l"(r) : "f"(x), "f"(y));
    return r;
}
__device__ __forceinline__ float2 unpack2(u64 v) {
    float2 r;
    asm("mov.b64 {%0, %1}, %2;" : "=f"(r.x), "=f"(r.y) : "l"(v));
    return r;
}

// cp.async helpers
__device__ __forceinline__ void cp16(unsigned dst, const float* src) {
    asm volatile("cp.async.ca.shared.global [%0], [%1], 16;" :: "r"(dst), "l"(src));
}
__device__ __forceinline__ void cp_commit() {
    asm volatile("cp.async.commit_group;");
}
template <int N>
__device__ __forceinline__ void cp_wait() {
    asm volatile("cp.async.wait_group %0;" :: "n"(N));
}

// ---------------------------------------------------------------------------
// Kernel A: partial kv_mul.
// 256-thread block = 4 split-K sub-groups of 64 threads. Each sub-group's
// 8x8 thread grid covers the FULL 64x64 output with 8(c) x 8(d) register
// tiles (32 f32x2 accumulators), accumulating over its private 256 tokens.
// Keys read as native f32x2 pairs from smem; values duplicated via mov.b64.
// cp.async double-buffered staging; deterministic staged in-block reduction.
// ---------------------------------------------------------------------------
__global__ __launch_bounds__(256, 2) void kv_partial_kernel(
    const float* __restrict__ Kg, const float* __restrict__ Vg)
{
    // [buffer][k/v][row = group*8 + t][padded 68 floats] = 34,816 B
    __shared__ __align__(16) float s_stage[2][2][NGROUPS * STAGE_T][RP];

    const int b   = blockIdx.y;
    const int s   = blockIdx.x;
    const int tid = threadIdx.x;
    const int g   = tid >> 6;          // sub-group 0..3
    const int gt  = tid & 63;
    const int c0  = (gt >> 3) * 8;     // tile c origin
    const int d0  = (gt & 7) * 8;      // tile d origin

    // --- cp.async chunk mapping: 1024 16B-chunks per stage, 4 per thread ---
    const float* srcs[4];
    unsigned dst0[4], dst1[4];
    #pragma unroll
    for (int j = 0; j < 4; ++j) {
        int ch  = tid + j * 256;       // 0..1023
        int arr = ch >> 9;             // 0=k, 1=v
        int wi  = ch & 511;
        int row = wi >> 4;             // 0..31  (= group*8 + token-in-stage)
        int c4  = wi & 15;             // 16B chunk within 256B token row
        int gr  = row >> 3, tl = row & 7;
        size_t tok = (size_t)b * TOK + (size_t)s * TPS + (size_t)gr * TPG + tl;
        srcs[j] = (arr == 0 ? Kg : Vg) + tok * C + c4 * 4;
        dst0[j] = (unsigned)__cvta_generic_to_shared(&s_stage[0][arr][row][c4 * 4]);
        dst1[j] = (unsigned)__cvta_generic_to_shared(&s_stage[1][arr][row][c4 * 4]);
    }

    // Prologue: stages 0 and 1 (stage advance = STAGE_T*C = 512 floats)
    #pragma unroll
    for (int j = 0; j < 4; ++j) cp16(dst0[j], srcs[j]);
    cp_commit();
    #pragma unroll
    for (int j = 0; j < 4; ++j) cp16(dst1[j], srcs[j] + 512);
    cp_commit();

    u64 acc[4][8];   // [c-pair][d]
    #pragma unroll
    for (int i = 0; i < 4; ++i)
        #pragma unroll
        for (int d = 0; d < 8; ++d) acc[i][d] = 0ull;

    for (int it = 0; it < NSTAGES; ++it) {
        if (it < NSTAGES - 1) cp_wait<1>(); else cp_wait<0>();
        __syncthreads();
        const int buf = it & 1;

        #pragma unroll
        for (int t = 0; t < STAGE_T; ++t) {
            const int r = g * STAGE_T + t;
            ulonglong2 ka = *(const ulonglong2*)&s_stage[buf][0][r][c0];     // {k0,k1},{k2,k3}
            ulonglong2 kb = *(const ulonglong2*)&s_stage[buf][0][r][c0 + 4]; // {k4,k5},{k6,k7}
            float4 va = *(const float4*)&s_stage[buf][1][r][d0];
            float4 vb = *(const float4*)&s_stage[buf][1][r][d0 + 4];
            u64 vd0 = pack2(va.x, va.x), vd1 = pack2(va.y, va.y);
            u64 vd2 = pack2(va.z, va.z), vd3 = pack2(va.w, va.w);
            u64 vd4 = pack2(vb.x, vb.x), vd5 = pack2(vb.y, vb.y);
            u64 vd6 = pack2(vb.z, vb.z), vd7 = pack2(vb.w, vb.w);
            u64 vd[8] = {vd0, vd1, vd2, vd3, vd4, vd5, vd6, vd7};
            #pragma unroll
            for (int d = 0; d < 8; ++d) {
                acc[0][d] = fma2(ka.x, vd[d], acc[0][d]);
                acc[1][d] = fma2(ka.y, vd[d], acc[1][d]);
                acc[2][d] = fma2(kb.x, vd[d], acc[2][d]);
                acc[3][d] = fma2(kb.y, vd[d], acc[3][d]);
            }
        }
        __syncthreads();
        if (it + 2 < NSTAGES) {
            const float* adv = (const float*)0;
            (void)adv;
            #pragma unroll
            for (int j = 0; j < 4; ++j)
                cp16(buf == 0 ? dst0[j] : dst1[j], srcs[j] + (size_t)(it + 2) * 512);
            cp_commit();
        }
    }

    // --- deterministic staged in-block split-K reduction (g0 += g1 += g2 += g3) ---
    u64* s_red = (u64*)&s_stage[0][0][0][0];  // 2048 u64 = 16 KB (fits, staging done)
    #pragma unroll
    for (int rr = 1; rr < NGROUPS; ++rr) {
        if (g == rr) {
            u64* dst = &s_red[gt * 32];
            #pragma unroll
            for (int i = 0; i < 4; ++i)
                #pragma unroll
                for (int d = 0; d < 8; ++d) dst[i * 8 + d] = acc[i][d];
        }
        __syncthreads();
        if (g == 0) {
            const u64* src = &s_red[gt * 32];
            #pragma unroll
            for (int i = 0; i < 4; ++i)
                #pragma unroll
                for (int d = 0; d < 8; ++d) acc[i][d] = add2(acc[i][d], src[i * 8 + d]);
        }
        __syncthreads();
    }

    if (g == 0) {
        float* outp = &g_partial[((size_t)(b * SPLITS + s)) * (C * C)];
        #pragma unroll
        for (int i = 0; i < 4; ++i) {
            float2 u[8];
            #pragma unroll
            for (int d = 0; d < 8; ++d) u[d] = unpack2(acc[i][d]);
            *(float4*)&outp[(c0 + 2 * i) * C + d0]         = make_float4(u[0].x, u[1].x, u[2].x, u[3].x);
            *(float4*)&outp[(c0 + 2 * i) * C + d0 + 4]     = make_float4(u[4].x, u[5].x, u[6].x, u[7].x);
            *(float4*)&outp[(c0 + 2 * i + 1) * C + d0]     = make_float4(u[0].y, u[1].y, u[2].y, u[3].y);
            *(float4*)&outp[(c0 + 2 * i + 1) * C + d0 + 4] = make_float4(u[4].y, u[5].y, u[6].y, u[7].y);
        }
    }
}

// ---------------------------------------------------------------------------
// Kernel B: deterministic split reduction (vectorized float4).
// ---------------------------------------------------------------------------
__global__ void kv_reduce_kernel()
{
    int q = blockIdx.x * 256 + threadIdx.x;    // 0..4095 (float4 index)
    int b   = q >> 10;
    int cd4 = q & 1023;
    const float4* p = (const float4*)&g_partial[(size_t)b * SPLITS * (C * C)] + cd4;
    float4 sv = make_float4(0.f, 0.f, 0.f, 0.f);
    #pragma unroll 4
    for (int i = 0; i < SPLITS; ++i) {
        float4 t = p[(size_t)i * 1024];
        sv.x += t.x; sv.y += t.y; sv.z += t.z; sv.w += t.w;
    }
    ((float4*)g_kv)[q] = sv;
}

// ---------------------------------------------------------------------------
// Kernel C: softmax over the C axis. One thread per (b, d) column.
// ---------------------------------------------------------------------------
__global__ void softmax_kernel()
{
    int tid = threadIdx.x;
    int b = tid >> 6;
    int d = tid & 63;
    const float* in = &g_kv[b * (C * C) + d];
    float*      out = &g_sm[b * (C * C) + d];

    float m = -3.402823466e38f;
    for (int c = 0; c < C; ++c) m = fmaxf(m, in[c * C]);
    float sum = 0.f;
    for (int c = 0; c < C; ++c) {
        float e = expf(in[c * C] - m);
        out[c * C] = e;
        sum += e;
    }
    float inv = 1.f / sum;
    for (int c = 0; c < C; ++c) out[c * C] *= inv;
}

// ---------------------------------------------------------------------------
// Kernel D: out[b,r,d] = alpha * sum_c key_cur[b,r,c] * sm[b,c,d] + val_cur.
// 128-thread block handles 64 rows. Thread = 4 rows x 8 d (32 f32x2 accs);
// sm row loads amortized over 4 rows, key loads vectorized over c.
// ---------------------------------------------------------------------------
__global__ __launch_bounds__(128) void out_kernel(
    const float* __restrict__ key_cur, const float* __restrict__ val_cur,
    const float* __restrict__ alpha, float* __restrict__ out)
{
    __shared__ __align__(16) float s_sm[C * C];     // [c][d], 16 KB
    __shared__ __align__(16) float s_key[64][RP];   // padded rows

    const int b   = blockIdx.y;
    const int rb  = blockIdx.x;        // 0..255
    const int tid = threadIdx.x;

    // load softmaxed kv matrix (1024 float4)
    const float* smg = &g_sm[b * (C * C)];
    #pragma unroll
    for (int j = 0; j < 8; ++j) {
        int q = j * 128 + tid;
        *(float4*)&s_sm[q * 4] = *(const float4*)&smg[q * 4];
    }
    // load 64 key rows
    const float* kg = &key_cur[((size_t)b * NROWS + (size_t)rb * 64) * C];
    #pragma unroll
    for (int j = 0; j < 8; ++j) {
        int q = j * 128 + tid;
        int row = q >> 4, c4 = q & 15;
        *(float4*)&s_key[row][c4 * 4] = *(const float4*)&kg[q * 4];
    }
    __syncthreads();

    const int rg = tid >> 3;     // 0..15
    const int dg = tid & 7;      // 0..7
    const int r0 = rg * 4, d0 = dg * 8;

    u64 acc[4][4];               // [row][d-pair]
    #pragma unroll
    for (int i = 0; i < 4; ++i)
        #pragma unroll
        for (int p = 0; p < 4; ++p) acc[i][p] = 0ull;

    for (int c = 0; c < C; c += 4) {
        float kk[4][4];
        #pragma unroll
        for (int i = 0; i < 4; ++i) {
            float4 t = *(const float4*)&s_key[r0 + i][c];
            kk[i][0] = t.x; kk[i][1] = t.y; kk[i][2] = t.z; kk[i][3] = t.w;
        }
        #pragma unroll
        for (int cc = 0; cc < 4; ++cc) {
            ulonglong2 sa = *(const ulonglong2*)&s_sm[(c + cc) * C + d0];
            ulonglong2 sb = *(const ulonglong2*)&s_sm[(c + cc) * C + d0 + 4];
            #pragma unroll
            for (int i = 0; i < 4; ++i) {
                u64 kd = pack2(kk[i][cc], kk[i][cc]);
                acc[i][0] = fma2(kd, sa.x, acc[i][0]);
                acc[i][1] = fma2(kd, sa.y, acc[i][1]);
                acc[i][2] = fma2(kd, sb.x, acc[i][2]);
                acc[i][3] = fma2(kd, sb.y, acc[i][3]);
            }
        }
    }

    const float a = alpha[0];
    #pragma unroll
    for (int i = 0; i < 4; ++i) {
        size_t base = ((size_t)b * NROWS + (size_t)rb * 64 + r0 + i) * C + d0;
        float4 v0 = *(const float4*)&val_cur[base];
        float4 v1 = *(const float4*)&val_cur[base + 4];
        float2 x0 = unpack2(acc[i][0]), x1 = unpack2(acc[i][1]);
        float2 x2 = unpack2(acc[i][2]), x3 = unpack2(acc[i][3]);
        float4 o0 = make_float4(a * x0.x + v0.x, a * x0.y + v0.y,
                                a * x1.x + v0.z, a * x1.y + v0.w);
        float4 o1 = make_float4(a * x2.x + v1.x, a * x2.y + v1.y,
                                a * x3.x + v1.z, a * x3.y + v1.w);
        *(float4*)&out[base]     = o0;
        *(float4*)&out[base + 4] = o1;
    }
}

// ---------------------------------------------------------------------------
extern "C" void kernel_launch(void* const* d_in, const int* in_sizes, int n_in,
                              void* d_out, int out_size)
{
    const float* key_mem = (const float*)d_in[0];
    const float* val_mem = (const float*)d_in[1];
    const float* key_cur = (const float*)d_in[2];
    const float* val_cur = (const float*)d_in[3];
    const float* alpha   = (const float*)d_in[4];
    float* out = (float*)d_out;

    kv_partial_kernel<<<dim3(SPLITS, NB), 256>>>(key_mem, val_mem);
    kv_reduce_kernel<<<16, 256>>>();
    softmax_kernel<<<1, 256>>>();
    out_kernel<<<dim3(NROWS / 64, NB), 128>>>(key_cur, val_cur, alpha, out);
}